// round 4
// baseline (speedup 1.0000x reference)
#include <cuda_runtime.h>
#include <math.h>

#define B_    256
#define T_    128
#define HID_  1440
#define NORN  384
#define NPN   112
#define NLN   64
#define NKC   864
#define NMB   16
#define NCTA  148
#define YSIZE ((size_t)B_ * T_ * HID_)

// ---------------- persistent device state ----------------
__device__ float S_orn [2][B_ * NORN];
__device__ float S_pn  [2][B_ * NPN ];
__device__ float S_ln  [2][B_ * NLN ];
__device__ float S_kc  [2][B_ * NKC ];
__device__ float S_mbon[2][B_ * NMB ];
__device__ float S_kcpre[B_ * NKC];
__device__ float g_X [(size_t)T_ * B_ * NORN];   // x_t = obs@W_in^T + b_in
__device__ float g_mh[(size_t)T_ * B_ * NMB];    // mbon after each outer step
__device__ unsigned g_barcnt;
__device__ unsigned g_bargen;
__device__ unsigned g_done;

// ---------------- grid barrier (monotone generation) ----------------
__device__ __forceinline__ void gsync(unsigned n) {
    __syncthreads();
    if (threadIdx.x == 0) {
        __threadfence();
        unsigned prev = atomicAdd(&g_barcnt, 1u);
        if (prev == gridDim.x - 1u) {
            g_barcnt = 0;
            __threadfence();
            *(volatile unsigned*)&g_bargen = n;
        } else {
            while (*(volatile unsigned*)&g_bargen < n) { }
        }
        __threadfence();
    }
    __syncthreads();
}

struct Src { const float* A; const float* W; int D; };

// ---------------- 32(batch) x 32(out) tile, 256 threads ----------------
__device__ __forceinline__ void tile32(
    float* __restrict__ out, float* __restrict__ out2,
    int Ostride, int Oreal, int b0, int o0,
    const Src* srcs, int ns,
    const float* __restrict__ bias,
    const float* __restrict__ extra,
    bool dotanh,
    float* As, float* Ws)
{
    float a00 = 0.f, a01 = 0.f, a10 = 0.f, a11 = 0.f;
    const int tid = threadIdx.x;
    const int tx = tid & 15, ty = tid >> 4;
    const int lb = tid >> 3, lk = (tid & 7) << 2;

    for (int s = 0; s < ns; ++s) {
        const float* A = srcs[s].A;
        const float* W = srcs[s].W;
        const int    D = srcs[s].D;
        for (int k0 = 0; k0 < D; k0 += 32) {
            float4 va = make_float4(0.f, 0.f, 0.f, 0.f);
            if (k0 + lk < D)
                va = __ldcg(reinterpret_cast<const float4*>(A + (size_t)(b0 + lb) * D + k0 + lk));
            As[(lk + 0) * 34 + lb] = va.x;
            As[(lk + 1) * 34 + lb] = va.y;
            As[(lk + 2) * 34 + lb] = va.z;
            As[(lk + 3) * 34 + lb] = va.w;

            float4 vw = make_float4(0.f, 0.f, 0.f, 0.f);
            if (k0 + lk < D && o0 + lb < Oreal)
                vw = *reinterpret_cast<const float4*>(W + (size_t)(o0 + lb) * D + k0 + lk);
            Ws[(lk + 0) * 34 + lb] = vw.x;
            Ws[(lk + 1) * 34 + lb] = vw.y;
            Ws[(lk + 2) * 34 + lb] = vw.z;
            Ws[(lk + 3) * 34 + lb] = vw.w;
            __syncthreads();
#pragma unroll
            for (int k = 0; k < 32; ++k) {
                float2 av = *reinterpret_cast<const float2*>(&As[k * 34 + ty * 2]);
                float2 wv = *reinterpret_cast<const float2*>(&Ws[k * 34 + tx * 2]);
                a00 += av.x * wv.x; a01 += av.x * wv.y;
                a10 += av.y * wv.x; a11 += av.y * wv.y;
            }
            __syncthreads();
        }
    }

    const int og = o0 + tx * 2;
#pragma unroll
    for (int j = 0; j < 2; ++j) {
        int o = og + j;
        if (o < Oreal) {
            float bv = bias ? bias[o] : 0.f;
#pragma unroll
            for (int i = 0; i < 2; ++i) {
                int b = b0 + ty * 2 + i;
                float v = (j == 0 ? (i == 0 ? a00 : a10) : (i == 0 ? a01 : a11)) + bv;
                if (extra) v += __ldcg(extra + (size_t)b * Ostride + o);
                if (dotanh) v = tanhf(v);
                out[(size_t)b * Ostride + o] = v;
                if (out2) out2[(size_t)b * Ostride + o] = v;
            }
        }
    }
}

// ---------------- init: scatter h into state buffers (buf 0) ----------------
__global__ void k_init(const float* __restrict__ h) {
    const int b = blockIdx.x;
    for (int i = threadIdx.x; i < HID_; i += blockDim.x) {
        float v = h[(size_t)b * HID_ + i];
        if      (i < 384)  S_orn [0][b * NORN + i]          = v;
        else if (i < 496)  S_pn  [0][b * NPN  + (i - 384)]  = v;
        else if (i < 560)  S_ln  [0][b * NLN  + (i - 496)]  = v;
        else if (i < 1424) S_kc  [0][b * NKC  + (i - 560)]  = v;
        else               S_mbon[0][b * NMB  + (i - 1424)] = v;
    }
}

// ---------------- X precompute: g_X[t][b][384] = obs[b][t]@Win^T + inb ----------------
__global__ void k_X(const float* __restrict__ obs, const float* __restrict__ Win,
                    const float* __restrict__ inb) {
    const int b0 = blockIdx.x * 32;
    const int t  = blockIdx.y;
    __shared__ __align__(16) float obs_s[32 * 64];
    const int tid = threadIdx.x;  // 384 threads
    for (int s4 = tid; s4 < 512; s4 += 384) {
        int b = s4 >> 4, kk = (s4 & 15) * 4;
        *reinterpret_cast<float4*>(&obs_s[b * 64 + kk]) =
            *reinterpret_cast<const float4*>(obs + ((size_t)(b0 + b) * T_ + t) * 64 + kk);
    }
    const int o = tid;  // < 384
    float wreg[64];
#pragma unroll
    for (int j = 0; j < 16; ++j) {
        float4 w = *reinterpret_cast<const float4*>(Win + (size_t)o * 64 + j * 4);
        wreg[j * 4 + 0] = w.x; wreg[j * 4 + 1] = w.y;
        wreg[j * 4 + 2] = w.z; wreg[j * 4 + 3] = w.w;
    }
    const float base = inb[o];
    __syncthreads();
    for (int b = 0; b < 32; ++b) {
        float acc = base;
#pragma unroll
        for (int j = 0; j < 16; ++j) {
            float4 ov = *reinterpret_cast<const float4*>(&obs_s[b * 64 + j * 4]);
            acc += ov.x * wreg[j * 4 + 0] + ov.y * wreg[j * 4 + 1]
                 + ov.z * wreg[j * 4 + 2] + ov.w * wreg[j * 4 + 3];
        }
        g_X[((size_t)t * B_ + (b0 + b)) * NORN + o] = acc;
    }
}

// ---------------- persistent recurrent kernel ----------------
__global__ void __launch_bounds__(256, 1)
k_persist(const float* __restrict__ Woto, const float* __restrict__ Wlto,
          const float* __restrict__ Wotp, const float* __restrict__ Wltp,
          const float* __restrict__ Wptp, const float* __restrict__ Wotl,
          const float* __restrict__ Wptl, const float* __restrict__ Wltl,
          const float* __restrict__ Wktk, const float* __restrict__ Wmtk,
          const float* __restrict__ Wptk, const float* __restrict__ Wktm,
          const float* __restrict__ born, const float* __restrict__ bpn,
          const float* __restrict__ bln,  const float* __restrict__ bkc,
          const float* __restrict__ bmbon)
{
    __shared__ __align__(16) float As[32 * 34];
    __shared__ __align__(16) float Ws[32 * 34];
    const int c = blockIdx.x;
    unsigned bt = 0;

#pragma unroll 1
    for (int s = 0; s < T_ * 4; ++s) {
        const int t = s >> 2, inner = s & 3;
        const int p = s & 1, q = p ^ 1;
        const float* Xt = g_X + (size_t)t * B_ * NORN;

        // ---- Phase 1: orn(new) + kc_pre ----
        {
            // kc_pre tiles: 216 (8 bt x 27 ot); orn tiles: 96 (8 bt x 12 ot)
            {   // kc_pre tile c (0..147)
                int id = c; int tb = id / 27, to = id % 27;
                Src ss[2] = { { S_kc[p],   Wktk, NKC },
                              { S_mbon[p], Wmtk, NMB } };
                tile32(S_kcpre, nullptr, NKC, NKC, tb * 32, to * 32,
                       ss, 2, nullptr, nullptr, false, As, Ws);
            }
            if (c < 68) {   // kc_pre tiles 148..215
                int id = 148 + c; int tb = id / 27, to = id % 27;
                Src ss[2] = { { S_kc[p],   Wktk, NKC },
                              { S_mbon[p], Wmtk, NMB } };
                tile32(S_kcpre, nullptr, NKC, NKC, tb * 32, to * 32,
                       ss, 2, nullptr, nullptr, false, As, Ws);
            } else {        // orn tiles 0..79
                int id = c - 68; int tb = id / 12, to = id % 12;
                Src ss[2] = { { S_orn[p], Woto, NORN },
                              { S_ln[p],  Wlto, NLN  } };
                tile32(S_orn[q], nullptr, NORN, NORN, tb * 32, to * 32,
                       ss, 2, born, Xt, true, As, Ws);
            }
            if (c >= 132) { // orn tiles 80..95
                int id = 80 + (c - 132); int tb = id / 12, to = id % 12;
                Src ss[2] = { { S_orn[p], Woto, NORN },
                              { S_ln[p],  Wlto, NLN  } };
                tile32(S_orn[q], nullptr, NORN, NORN, tb * 32, to * 32,
                       ss, 2, born, Xt, true, As, Ws);
            }
        }
        gsync(++bt);

        // ---- Phase 2: pn ----
        if (c < 32) {
            int tb = c >> 2, to = c & 3;
            Src ss[3] = { { S_orn[q], Wotp, NORN },
                          { S_ln[p],  Wltp, NLN  },
                          { S_pn[p],  Wptp, NPN  } };
            tile32(S_pn[q], nullptr, NPN, NPN, tb * 32, to * 32,
                   ss, 3, bpn, nullptr, true, As, Ws);
        }
        gsync(++bt);

        // ---- Phase 3: ln + kc finalize ----
        if (c < 16) {
            int tb = c >> 1, to = c & 1;
            Src ss[3] = { { S_orn[q], Wotl, NORN },
                          { S_pn[q],  Wptl, NPN  },
                          { S_ln[p],  Wltl, NLN  } };
            tile32(S_ln[q], nullptr, NLN, NLN, tb * 32, to * 32,
                   ss, 3, bln, nullptr, true, As, Ws);
        } else {
            int u = c - 16;   // 0..131
            {
                int tb = u / 27, to = u % 27;
                Src ss[1] = { { S_pn[q], Wptk, NPN } };
                tile32(S_kc[q], nullptr, NKC, NKC, tb * 32, to * 32,
                       ss, 1, bkc, S_kcpre, true, As, Ws);
            }
            if (u + 132 < 216) {
                int id = u + 132; int tb = id / 27, to = id % 27;
                Src ss[1] = { { S_pn[q], Wptk, NPN } };
                tile32(S_kc[q], nullptr, NKC, NKC, tb * 32, to * 32,
                       ss, 1, bkc, S_kcpre, true, As, Ws);
            }
        }
        gsync(++bt);

        // ---- Phase 4: mbon ----
        if (c < 8) {
            Src ss[1] = { { S_kc[q], Wktm, NKC } };
            float* out2 = (inner == 3) ? (g_mh + (size_t)t * B_ * NMB) : nullptr;
            tile32(S_mbon[q], out2, NMB, NMB, c * 32, 0,
                   ss, 1, bmbon, nullptr, true, As, Ws);
        }
        gsync(++bt);
    }

    // ---- reset barrier state for next graph replay ----
    __threadfence();
    if (threadIdx.x == 0) atomicAdd(&g_done, 1u);
    if (blockIdx.x == 0 && threadIdx.x == 0) {
        while (*(volatile unsigned*)&g_done < gridDim.x) { }
        g_done = 0;
        *(volatile unsigned*)&g_bargen = 0;
        __threadfence();
    }
}

// ---------------- readout: y[b][t][o] = mh[t][b]@rw[o] + rb[o] ----------------
__global__ void k_readout(const float* __restrict__ rw, const float* __restrict__ rb,
                          float* __restrict__ y) {
    const int b  = blockIdx.x;
    const int t0 = blockIdx.y * 8;
    __shared__ __align__(16) float mh[128];
    const int tid = threadIdx.x;
    if (tid < 128)
        mh[tid] = g_mh[((size_t)(t0 + (tid >> 4))) * B_ * NMB + (size_t)b * NMB + (tid & 15)];
    __syncthreads();
    for (int o = tid; o < HID_; o += 256) {
        float4 w0 = *reinterpret_cast<const float4*>(rw + (size_t)o * 16 + 0);
        float4 w1 = *reinterpret_cast<const float4*>(rw + (size_t)o * 16 + 4);
        float4 w2 = *reinterpret_cast<const float4*>(rw + (size_t)o * 16 + 8);
        float4 w3 = *reinterpret_cast<const float4*>(rw + (size_t)o * 16 + 12);
        float bo = rb[o];
#pragma unroll
        for (int tt = 0; tt < 8; ++tt) {
            float4 m0 = *reinterpret_cast<const float4*>(&mh[tt * 16 + 0]);
            float4 m1 = *reinterpret_cast<const float4*>(&mh[tt * 16 + 4]);
            float4 m2 = *reinterpret_cast<const float4*>(&mh[tt * 16 + 8]);
            float4 m3 = *reinterpret_cast<const float4*>(&mh[tt * 16 + 12]);
            float acc = bo
                + m0.x * w0.x + m0.y * w0.y + m0.z * w0.z + m0.w * w0.w
                + m1.x * w1.x + m1.y * w1.y + m1.z * w1.z + m1.w * w1.w
                + m2.x * w2.x + m2.y * w2.y + m2.z * w2.z + m2.w * w2.w
                + m3.x * w3.x + m3.y * w3.y + m3.z * w3.z + m3.w * w3.w;
            y[((size_t)b * T_ + (t0 + tt)) * HID_ + o] = acc;
        }
    }
}

// ---------------- h2 gather (final state, buf 0) ----------------
__global__ void k_h2(float* __restrict__ h2) {
    const int b = blockIdx.x;
    for (int i = threadIdx.x; i < HID_; i += blockDim.x) {
        float v;
        if      (i < 384)  v = S_orn [0][b * NORN + i];
        else if (i < 496)  v = S_pn  [0][b * NPN  + (i - 384)];
        else if (i < 560)  v = S_ln  [0][b * NLN  + (i - 496)];
        else if (i < 1424) v = S_kc  [0][b * NKC  + (i - 560)];
        else               v = S_mbon[0][b * NMB  + (i - 1424)];
        h2[(size_t)b * HID_ + i] = v;
    }
}

extern "C" void kernel_launch(void* const* d_in, const int* in_sizes, int n_in,
                              void* d_out, int out_size) {
    const float* obs   = (const float*)d_in[0];
    const float* h     = (const float*)d_in[1];
    const float* Win   = (const float*)d_in[2];
    const float* inb   = (const float*)d_in[3];
    const float* Woto  = (const float*)d_in[4];
    const float* Wlto  = (const float*)d_in[5];
    const float* Wotp  = (const float*)d_in[6];
    const float* Wltp  = (const float*)d_in[7];
    const float* Wptp  = (const float*)d_in[8];
    const float* Wotl  = (const float*)d_in[9];
    const float* Wptl  = (const float*)d_in[10];
    const float* Wltl  = (const float*)d_in[11];
    const float* Wktk  = (const float*)d_in[12];
    const float* Wmtk  = (const float*)d_in[13];
    const float* Wptk  = (const float*)d_in[14];
    const float* Wktm  = (const float*)d_in[15];
    const float* born  = (const float*)d_in[16];
    const float* bpn   = (const float*)d_in[17];
    const float* bln   = (const float*)d_in[18];
    const float* bkc   = (const float*)d_in[19];
    const float* bmbon = (const float*)d_in[20];
    const float* rw    = (const float*)d_in[21];
    const float* rb    = (const float*)d_in[22];
    float* out = (float*)d_out;

    k_init<<<B_, 256>>>(h);
    k_X<<<dim3(8, T_), 384>>>(obs, Win, inb);
    k_persist<<<NCTA, 256>>>(Woto, Wlto, Wotp, Wltp, Wptp, Wotl, Wptl, Wltl,
                             Wktk, Wmtk, Wptk, Wktm, born, bpn, bln, bkc, bmbon);
    k_readout<<<dim3(B_, 16), 256>>>(rw, rb, out);
    k_h2<<<B_, 256>>>(out + YSIZE);
}